// round 6
// baseline (speedup 1.0000x reference)
#include <cuda_runtime.h>
#include <cuda_bf16.h>
#include <cstdint>

#define N_NODES 16384
#define N_EDGES 65536

// Scratch for layer-1 output (h1), 16384 x 64 f32 = 4 MB.
__device__ float g_h1[N_NODES * 64];

// ---------- packed f32x2 helpers (Blackwell FFMA2; relu via 2x FMNMX) ----------
__device__ __forceinline__ unsigned long long ffma2(unsigned long long a,
                                                    unsigned long long b,
                                                    unsigned long long c) {
    unsigned long long d;
    asm("fma.rn.f32x2 %0, %1, %2, %3;" : "=l"(d) : "l"(a), "l"(b), "l"(c));
    return d;
}
__device__ __forceinline__ unsigned long long pack2(float x, float y) {
    unsigned long long r;
    asm("mov.b64 %0, {%1, %2};" : "=l"(r) : "f"(x), "f"(y));
    return r;
}
__device__ __forceinline__ float2 unpack2(unsigned long long v) {
    float2 f;
    asm("mov.b64 {%0, %1}, %2;" : "=f"(f.x), "=f"(f.y) : "l"(v));
    return f;
}
__device__ __forceinline__ unsigned long long relu2(unsigned long long v) {
    float2 f = unpack2(v);
    f.x = fmaxf(f.x, 0.f);
    f.y = fmaxf(f.y, 0.f);
    return pack2(f.x, f.y);
}

// ---------- cp.async helpers ----------
__device__ __forceinline__ void cpasync8(uint32_t dst_smem, const void* src) {
    asm volatile("cp.async.ca.shared.global [%0], [%1], 8;"
                 :: "r"(dst_smem), "l"(src));
}
#define CP_COMMIT() asm volatile("cp.async.commit_group;" ::: "memory")
#define CP_WAIT(n)  asm volatile("cp.async.wait_group %0;" :: "n"(n) : "memory")

// ---------------------------------------------------------------------------
// k_init1: h1[n,:] = x[n,:8] @ root1[8,64] + bias1. One warp per node.
// ---------------------------------------------------------------------------
__global__ void k_init1(const float* __restrict__ x,
                        const float* __restrict__ root1,
                        const float* __restrict__ bias1) {
    __shared__ float sroot[512];
    __shared__ float sbias[64];
    int t = threadIdx.x;
    for (int k = t; k < 512; k += 256) sroot[k] = root1[k];
    if (t < 64) sbias[t] = bias1[t];
    __syncthreads();

    int warp = t >> 5, lane = t & 31;
    int n = blockIdx.x * 8 + warp;
    float acc0 = sbias[lane], acc1 = sbias[lane + 32];
    const float* xr = x + n * 8;
#pragma unroll
    for (int i = 0; i < 8; i++) {
        float xv = __ldg(xr + i);
        acc0 = fmaf(xv, sroot[i * 64 + lane], acc0);
        acc1 = fmaf(xv, sroot[i * 64 + lane + 32], acc1);
    }
    g_h1[n * 64 + lane] = acc0;
    g_h1[n * 64 + lane + 32] = acc1;
}

// ---------------------------------------------------------------------------
// k_edge1: layer-1 edge messages (c_in=8 -> 4 i-pairs), packed f32x2,
// 8 edges per warp-iteration, atomically scattered into h1.
// edge_index is int32 (JAX x64 disabled).
// ---------------------------------------------------------------------------
#define EPB1 8
__global__ void __launch_bounds__(256, 2)
k_edge1(const float* __restrict__ x,
        const int* __restrict__ ei,
        const float* __restrict__ ea,
        const float* __restrict__ A1,
        const float* __restrict__ b1) {
    __shared__ float4 sWlo[4 * 32];   // [p][o] {P0,P1,Q0,Q1} for cols o
    __shared__ float4 sWhi[4 * 32];   // same for o+32
    __shared__ float4 sB[4 * 32];     // {Blo0,Blo1,Bhi0,Bhi1}
    __shared__ float  sx[8][EPB1 * 8];  // per warp: 8 edges x 8 feats

    int t = threadIdx.x;
    for (int k = t; k < 128; k += 256) {
        int p = k >> 5, o = k & 31;
        int i0 = 2 * p;
        sWlo[k] = make_float4(A1[i0 * 64 + o],       A1[(i0 + 1) * 64 + o],
                              A1[512 + i0 * 64 + o], A1[512 + (i0 + 1) * 64 + o]);
        sWhi[k] = make_float4(A1[i0 * 64 + o + 32],       A1[(i0 + 1) * 64 + o + 32],
                              A1[512 + i0 * 64 + o + 32], A1[512 + (i0 + 1) * 64 + o + 32]);
        sB[k]   = make_float4(b1[i0 * 64 + o],      b1[(i0 + 1) * 64 + o],
                              b1[i0 * 64 + o + 32], b1[(i0 + 1) * 64 + o + 32]);
    }
    __syncthreads();

    int warp = t >> 5, lane = t & 31;
    const unsigned long long* sx2 = (const unsigned long long*)sx[warp];
    const ulonglong2* pWlo = (const ulonglong2*)sWlo;
    const ulonglong2* pWhi = (const ulonglong2*)sWhi;
    const ulonglong2* pB   = (const ulonglong2*)sB;

    int gw = blockIdx.x * 8 + warp;
    int nwarps = gridDim.x * 8;
    const int* src = ei;
    const int* dst = ei + N_EDGES;

    for (int g = gw; g < N_EDGES / EPB1; g += nwarps) {
        int e0 = g * EPB1;
        {   // stage x rows: lane -> (edge = lane>>2, float2 j = lane&3)
            int e = lane >> 2, j = lane & 3;
            int s = src[e0 + e];
            float2 v = *(const float2*)(x + (size_t)s * 8 + j * 2);
            ((float2*)sx[warp])[e * 4 + j] = v;
        }
        unsigned long long a0d[EPB1], a1d[EPB1];
#pragma unroll
        for (int e = 0; e < EPB1; e++) {
            float2 at = *(const float2*)(ea + (size_t)(e0 + e) * 2);
            a0d[e] = pack2(at.x, at.x);
            a1d[e] = pack2(at.y, at.y);
        }
        __syncwarp();

        unsigned long long accL[EPB1], accH[EPB1];
#pragma unroll
        for (int e = 0; e < EPB1; e++) { accL[e] = 0ull; accH[e] = 0ull; }
#pragma unroll
        for (int p = 0; p < 4; p++) {
            ulonglong2 wlo = pWlo[p * 32 + lane];
            ulonglong2 whi = pWhi[p * 32 + lane];
            ulonglong2 bb  = pB[p * 32 + lane];     // .x={Blo0,Blo1} .y={Bhi0,Bhi1}
#pragma unroll
            for (int e = 0; e < EPB1; e++) {
                unsigned long long h2 = sx2[e * 4 + p];
                unsigned long long wl = ffma2(a0d[e], wlo.x, bb.x);
                wl = relu2(ffma2(a1d[e], wlo.y, wl));
                accL[e] = ffma2(h2, wl, accL[e]);
                unsigned long long wh = ffma2(a0d[e], whi.x, bb.y);
                wh = relu2(ffma2(a1d[e], whi.y, wh));
                accH[e] = ffma2(h2, wh, accH[e]);
            }
        }
#pragma unroll
        for (int e = 0; e < EPB1; e++) {
            int d = dst[e0 + e];
            float2 al = unpack2(accL[e]);
            float2 ah = unpack2(accH[e]);
            atomicAdd(&g_h1[d * 64 + lane],      al.x + al.y);
            atomicAdd(&g_h1[d * 64 + lane + 32], ah.x + ah.y);
        }
        __syncwarp();
    }
}

// ---------------------------------------------------------------------------
// k_init2: out[n,:] = h1[n,:64] @ root2[64,64] + bias2. 4 nodes per warp.
// ---------------------------------------------------------------------------
__global__ void k_init2(const float* __restrict__ root2,
                        const float* __restrict__ bias2,
                        float* __restrict__ out) {
    __shared__ float2 sR[64 * 32];
    __shared__ float  sb[64];
    int t = threadIdx.x;
    for (int k = t; k < 2048; k += 256) {
        int i = k >> 5, o = k & 31;
        sR[k] = make_float2(root2[i * 64 + o], root2[i * 64 + o + 32]);
    }
    if (t < 64) sb[t] = bias2[t];
    __syncthreads();

    int warp = t >> 5, lane = t & 31;
    int n0 = (blockIdx.x * 8 + warp) * 4;
    float hlo[4], hhi[4], acc0[4], acc1[4];
#pragma unroll
    for (int n = 0; n < 4; n++) {
        hlo[n] = g_h1[(n0 + n) * 64 + lane];
        hhi[n] = g_h1[(n0 + n) * 64 + lane + 32];
        acc0[n] = sb[lane];
        acc1[n] = sb[lane + 32];
    }
#pragma unroll
    for (int i = 0; i < 64; i++) {
        float2 r = sR[i * 32 + lane];
#pragma unroll
        for (int n = 0; n < 4; n++) {
            float hv = __shfl_sync(0xffffffffu, (i < 32) ? hlo[n] : hhi[n], i & 31);
            acc0[n] = fmaf(hv, r.x, acc0[n]);
            acc1[n] = fmaf(hv, r.y, acc1[n]);
        }
    }
#pragma unroll
    for (int n = 0; n < 4; n++) {
        out[(n0 + n) * 64 + lane]      = acc0[n];
        out[(n0 + n) * 64 + lane + 32] = acc1[n];
    }
}

// ---------------------------------------------------------------------------
// k_edge2: hot kernel. Packed-over-i f32x2, 8 edges/warp-iter, cp.async
// double-buffered h gather (hides L2 gather latency, 0 extra registers),
// 2 i-pairs per inner iteration (h loads as LDS.128).
//   msg[e,o] = sum_i h1[src[e],i] * relu(a0*P[i,o] + a1*Q[i,o] + B[i,o])
// smem: sWlo 16K | sWhi 16K | sB 16K | staging 2x16K = 81920 B.
// ---------------------------------------------------------------------------
#define EPB2 8
__global__ void __launch_bounds__(256, 2)
k_edge2(const int* __restrict__ ei,
        const float* __restrict__ ea,
        const float* __restrict__ A2,
        const float* __restrict__ b2,
        float* __restrict__ out) {
    extern __shared__ float smem[];
    float4* sWlo = (float4*)smem;                       // [32p][32o] {P0,P1,Q0,Q1}
    float4* sWhi = (float4*)(smem + 4096);              // same for o+32
    float4* sB   = (float4*)(smem + 8192);              // {Blo0,Blo1,Bhi0,Bhi1}
    float*  sh   = smem + 12288;                        // 2 bufs x 8 warps x 512 f32

    int t = threadIdx.x;
    for (int k = t; k < 1024; k += 256) {
        int p = k >> 5, o = k & 31;
        int i0 = 2 * p;
        sWlo[k] = make_float4(A2[i0 * 64 + o],        A2[(i0 + 1) * 64 + o],
                              A2[4096 + i0 * 64 + o], A2[4096 + (i0 + 1) * 64 + o]);
        sWhi[k] = make_float4(A2[i0 * 64 + o + 32],        A2[(i0 + 1) * 64 + o + 32],
                              A2[4096 + i0 * 64 + o + 32], A2[4096 + (i0 + 1) * 64 + o + 32]);
        sB[k]   = make_float4(b2[i0 * 64 + o],      b2[(i0 + 1) * 64 + o],
                              b2[i0 * 64 + o + 32], b2[(i0 + 1) * 64 + o + 32]);
    }
    __syncthreads();

    int warp = t >> 5, lane = t & 31;
    const ulonglong2* pWlo = (const ulonglong2*)sWlo;
    const ulonglong2* pWhi = (const ulonglong2*)sWhi;
    const ulonglong2* pB   = (const ulonglong2*)sB;

    float* shw[2];
    shw[0] = sh + warp * 512;
    shw[1] = sh + 8 * 512 + warp * 512;
    uint32_t shwa[2];
    shwa[0] = (uint32_t)__cvta_generic_to_shared(shw[0]);
    shwa[1] = (uint32_t)__cvta_generic_to_shared(shw[1]);

    int gw = blockIdx.x * 8 + warp;
    int nwarps = gridDim.x * 8;
    const int* src = ei;
    const int* dst = ei + N_EDGES;
    const int ngroups = N_EDGES / EPB2;

    // prologue: prefetch first group into buf 0
    if (gw < ngroups) {
        int e0 = gw * EPB2;
#pragma unroll
        for (int e = 0; e < EPB2; e++) {
            int s = src[e0 + e];
            cpasync8(shwa[0] + (e * 64 + lane * 2) * 4, &g_h1[(size_t)s * 64 + lane * 2]);
        }
        CP_COMMIT();
    }

    int buf = 0;
    for (int g = gw; g < ngroups; g += nwarps) {
        int gn = g + nwarps;
        if (gn < ngroups) {   // prefetch next group into the other buffer
            int en = gn * EPB2;
#pragma unroll
            for (int e = 0; e < EPB2; e++) {
                int s = src[en + e];
                cpasync8(shwa[buf ^ 1] + (e * 64 + lane * 2) * 4,
                         &g_h1[(size_t)s * 64 + lane * 2]);
            }
            CP_COMMIT();
            CP_WAIT(1);       // current group's data done
        } else {
            CP_WAIT(0);
        }
        __syncwarp();

        int e0 = g * EPB2;
        unsigned long long a0d[EPB2], a1d[EPB2];
#pragma unroll
        for (int e = 0; e < EPB2; e++) {
            float2 at = *(const float2*)(ea + (size_t)(e0 + e) * 2);
            a0d[e] = pack2(at.x, at.x);
            a1d[e] = pack2(at.y, at.y);
        }
        const ulonglong2* psh = (const ulonglong2*)shw[buf];

        unsigned long long accL[EPB2], accH[EPB2];
#pragma unroll
        for (int e = 0; e < EPB2; e++) { accL[e] = 0ull; accH[e] = 0ull; }
#pragma unroll 2
        for (int q = 0; q < 16; q++) {          // 2 i-pairs per iteration
            int p0 = 2 * q, p1 = 2 * q + 1;
            ulonglong2 wlo0 = pWlo[p0 * 32 + lane];
            ulonglong2 whi0 = pWhi[p0 * 32 + lane];
            ulonglong2 bb0  = pB[p0 * 32 + lane];
            ulonglong2 wlo1 = pWlo[p1 * 32 + lane];
            ulonglong2 whi1 = pWhi[p1 * 32 + lane];
            ulonglong2 bb1  = pB[p1 * 32 + lane];
#pragma unroll
            for (int e = 0; e < EPB2; e++) {
                ulonglong2 h4 = psh[e * 16 + q];   // {h[4q..4q+1], h[4q+2..4q+3]} broadcast
                unsigned long long wl = ffma2(a0d[e], wlo0.x, bb0.x);
                wl = relu2(ffma2(a1d[e], wlo0.y, wl));
                accL[e] = ffma2(h4.x, wl, accL[e]);
                unsigned long long wh = ffma2(a0d[e], whi0.x, bb0.y);
                wh = relu2(ffma2(a1d[e], whi0.y, wh));
                accH[e] = ffma2(h4.x, wh, accH[e]);
                wl = ffma2(a0d[e], wlo1.x, bb1.x);
                wl = relu2(ffma2(a1d[e], wlo1.y, wl));
                accL[e] = ffma2(h4.y, wl, accL[e]);
                wh = ffma2(a0d[e], whi1.x, bb1.y);
                wh = relu2(ffma2(a1d[e], whi1.y, wh));
                accH[e] = ffma2(h4.y, wh, accH[e]);
            }
        }
#pragma unroll
        for (int e = 0; e < EPB2; e++) {
            int d = dst[e0 + e];
            float2 al = unpack2(accL[e]);
            float2 ah = unpack2(accH[e]);
            atomicAdd(&out[d * 64 + lane],      al.x + al.y);
            atomicAdd(&out[d * 64 + lane + 32], ah.x + ah.y);
        }
        __syncwarp();
        buf ^= 1;
    }
}

// ---------------------------------------------------------------------------
// Launch: init1 -> edge1 -> init2 -> edge2 (default stream, graph-capturable).
// Inputs (metadata order):
//   0 x[16384,8] f32 | 1 edge_index[2,65536] i32 | 2 edge_attr[65536,2] f32
//   3 A1[2,512] | 4 b1[512] | 5 A2[2,4096] | 6 b2[4096]
//   7 root1[8,64] | 8 bias1[64] | 9 root2[64,64] | 10 bias2[64]
// ---------------------------------------------------------------------------
extern "C" void kernel_launch(void* const* d_in, const int* in_sizes, int n_in,
                              void* d_out, int out_size) {
    const float* x     = (const float*)d_in[0];
    const int*   ei    = (const int*)d_in[1];
    const float* ea    = (const float*)d_in[2];
    const float* A1    = (const float*)d_in[3];
    const float* b1    = (const float*)d_in[4];
    const float* A2    = (const float*)d_in[5];
    const float* b2    = (const float*)d_in[6];
    const float* root1 = (const float*)d_in[7];
    const float* bias1 = (const float*)d_in[8];
    const float* root2 = (const float*)d_in[9];
    const float* bias2 = (const float*)d_in[10];
    float* out = (float*)d_out;

    const int smem2 = 81920;  // 48K weights + 2x16K staging
    cudaFuncSetAttribute(k_edge2, cudaFuncAttributeMaxDynamicSharedMemorySize, smem2);

    k_init1<<<N_NODES / 8, 256>>>(x, root1, bias1);
    k_edge1<<<296, 256>>>(x, ei, ea, A1, b1);
    k_init2<<<N_NODES / 32, 256>>>(root2, bias2, out);
    k_edge2<<<296, 256, smem2>>>(ei, ea, A2, b2, out);
}